// round 11
// baseline (speedup 1.0000x reference)
#include <cuda_runtime.h>
#include <cstdint>

// Problem constants
#define Bn 8
#define Cn 256
#define Hn 96
#define Wn 128
#define Dd 4
#define NS 9      // 2*D+1
#define Qn 81     // NS*NS
#define HW (Hn*Wn)

// Tiling: 2 rows per block; RX=8; 288 consumer + 96 producer threads
#define TY 2
#define RX 8
#define XG (Wn/RX)            // 16
#define CONS (TY*XG*NS)       // 288 consumer threads (9 warps)
#define PROD 96               // 3 producer warps
#define NTHREADS (CONS+PROD)  // 384 (12 warps)
#define CC 16
#define NCHUNK (Cn/CC)        // 16
#define FBW (Wn + 2*Dd)       // 136
#define FBH (TY + 2*Dd)       // 10
#define VW (RX + 2*Dd)        // 16 window floats per thread

#define FA_FLOATS (CC*TY*Wn)          // 4096
#define FB_FLOATS (CC*FBH*FBW)        // 21760
#define STAGE_FLOATS (FA_FLOATS + FB_FLOATS)   // 25856
#define NA_FLOATS (TY*Wn)             // 256  (inva tile)
#define NB_FLOATS (FBH*FBW)           // 1360 (invb halo tile)
#define SMEM_BYTES ((2*STAGE_FLOATS + NA_FLOATS + NB_FLOATS)*4)  // 213312

// per-channel loader slots: fa 64, fb 340 -> 404 total
#define FA_SL (TY*(Wn/4))             // 64
#define FB_SL (FBH*(FBW/4))           // 340
#define TOT_SL (FA_SL+FB_SL)          // 404
#define PSL 5                         // ceil(404/96)

// named barrier ids (0 reserved)
#define BFULL0 1
#define BFULL1 2
#define BEMPTY0 3
#define BEMPTY1 4
#define BNORM 5

// bank-quad swizzle on 16B-unit index within a row
__device__ __host__ __forceinline__ int sw(int u) { return u ^ ((u >> 3) & 1); }

// ---------------------------------------------------------------------------
__device__ __forceinline__ void cp16(uint32_t saddr, const float* g, int nbytes) {
    asm volatile("cp.async.cg.shared.global [%0], [%1], 16, %2;"
                 :: "r"(saddr), "l"(g), "r"(nbytes));
}
__device__ __forceinline__ void bar_sync(int id) {
    asm volatile("bar.sync %0, %1;" :: "r"(id), "n"(NTHREADS) : "memory");
}
__device__ __forceinline__ void bar_arrive(int id) {
    asm volatile("bar.arrive %0, %1;" :: "r"(id), "n"(NTHREADS) : "memory");
}

// ---------------------------------------------------------------------------
// Fully fused correlation kernel (single launch).
// Producers (3 warps): cp.async all fa/fb slots per chunk, AND accumulate
//   fa^2 / fb^2 over channels for their own slots -> publish inva/invb tiles
//   in smem (split-phase BNORM barrier).
// Consumers (9 warps): thread = (yl, 8 x-pixels, dy=warp) -> 72 acc.
//   Per channel: 2 LDS.128 fa + 4 LDS.128 fb -> 72 FFMA.
// ---------------------------------------------------------------------------
__global__ void __launch_bounds__(NTHREADS, 1)
corr_kernel(const float* __restrict__ fa,
            const float* __restrict__ fb,
            float* __restrict__ out) {
    extern __shared__ float smem[];

    const int b   = blockIdx.y;
    const int y0  = blockIdx.x * TY;
    const int tid = threadIdx.x;

    const size_t baseA = (size_t)b * Cn * HW;
    const uint32_t smem_u = (uint32_t)__cvta_generic_to_shared(smem);
    float* s_na = smem + 2 * STAGE_FLOATS;       // inva [TY*Wn]
    float* s_nb = s_na + NA_FLOATS;              // invb halo [FBH*FBW]

    if (tid >= CONS) {
        // ================= PRODUCER =================
        const int ptid = tid - CONS;   // 0..95
        const float* ld_ptr[PSL];
        int ld_s[PSL], ld_str[PSL], ld_nb[PSL], ld_nd[PSL];
#pragma unroll
        for (int k = 0; k < PSL; k++) {
            int slot = ptid + k * PROD;
            ld_ptr[k] = nullptr; ld_s[k] = 0; ld_str[k] = 0;
            ld_nb[k] = -1; ld_nd[k] = 0;
            if (slot < TOT_SL) {
                if (slot < FA_SL) {
                    int yy = slot / (Wn / 4);
                    int u  = slot % (Wn / 4);
                    ld_nb[k]  = 16;
                    ld_ptr[k] = fa + baseA + (y0 + yy) * Wn + u * 4;
                    ld_s[k]   = yy * Wn + sw(u) * 4;
                    ld_str[k] = TY * Wn;
                    ld_nd[k]  = yy * Wn + u * 4;               // into s_na
                } else {
                    int u  = slot - FA_SL;
                    int hr = u / (FBW / 4);
                    int kk = u % (FBW / 4);
                    int yy = y0 - Dd + hr;
                    bool valid = (yy >= 0) && (yy < Hn) && (kk >= 1) && (kk <= Wn / 4);
                    ld_nb[k]  = valid ? 16 : 0;   // zfill halo/OOB
                    int yyc = min(max(yy, 0), Hn - 1);
                    int kc  = min(max(kk, 1), Wn / 4);
                    ld_ptr[k] = fb + baseA + yyc * Wn + kc * 4 - 4;
                    ld_s[k]   = FA_FLOATS + hr * FBW + sw(kk) * 4;
                    ld_str[k] = FBH * FBW;
                    ld_nd[k]  = NA_FLOATS + hr * FBW + kk * 4;  // into s_nb
                }
            }
        }

        float sq[PSL][4];
#pragma unroll
        for (int k = 0; k < PSL; k++)
#pragma unroll
            for (int j = 0; j < 4; j++) sq[k][j] = 0.f;

        int st = 0;
        for (int ch = 0; ch < NCHUNK; ch++) {
            bar_sync(BEMPTY0 + st);
            const int c0 = ch * CC;
            const uint32_t sb = smem_u + (uint32_t)(st * STAGE_FLOATS * 4);
#pragma unroll
            for (int k = 0; k < PSL; k++) {
                if (ld_nb[k] >= 0) {
                    const float* g = ld_ptr[k] + (size_t)c0 * HW;
                    const uint32_t sofs = sb + (uint32_t)(ld_s[k] * 4);
#pragma unroll
                    for (int cc = 0; cc < CC; cc++)
                        cp16(sofs + (uint32_t)(cc * ld_str[k] * 4),
                             g + (size_t)cc * HW, ld_nb[k]);
                }
            }
            asm volatile("cp.async.commit_group;");
            asm volatile("cp.async.wait_group 0;");
            bar_arrive(BFULL0 + st);

            // squared-sum accumulation on this thread's OWN slots
            const float* sbase = smem + st * STAGE_FLOATS;
#pragma unroll
            for (int k = 0; k < PSL; k++) {
                if (ld_nb[k] >= 0) {
                    const float* p = sbase + ld_s[k];
#pragma unroll
                    for (int cc = 0; cc < CC; cc++) {
                        float4 v = *(const float4*)(p + cc * ld_str[k]);
                        sq[k][0] = fmaf(v.x, v.x, sq[k][0]);
                        sq[k][1] = fmaf(v.y, v.y, sq[k][1]);
                        sq[k][2] = fmaf(v.z, v.z, sq[k][2]);
                        sq[k][3] = fmaf(v.w, v.w, sq[k][3]);
                    }
                }
            }
            st ^= 1;
        }

        // publish inverse norms (zfill slots -> huge inv, but acc==0 there)
#pragma unroll
        for (int k = 0; k < PSL; k++) {
            if (ld_nb[k] >= 0) {
                float4 iv;
                iv.x = 1.0f / fmaxf(sqrtf(sq[k][0]), 1e-12f);
                iv.y = 1.0f / fmaxf(sqrtf(sq[k][1]), 1e-12f);
                iv.z = 1.0f / fmaxf(sqrtf(sq[k][2]), 1e-12f);
                iv.w = 1.0f / fmaxf(sqrtf(sq[k][3]), 1e-12f);
                *(float4*)(s_na + ld_nd[k]) = iv;
            }
        }
        bar_arrive(BNORM);
        return;
    }

    // ================= CONSUMER =================
    const int dy = tid / 32;                 // 0..8 (one dy per warp)
    const int r  = tid % 32;
    const int yl = r / XG;                   // 0..1
    const int xg = r % XG;                   // 0..15
    const int x0 = xg * RX;

    // swizzled, channel-invariant float offsets
    int faO[2], fbO[4];
#pragma unroll
    for (int j = 0; j < 2; j++)
        faO[j] = yl * Wn + sw(2 * xg + j) * 4;
#pragma unroll
    for (int j = 0; j < 4; j++)
        fbO[j] = (yl + dy) * FBW + sw(2 * xg + j) * 4;

    float acc[NS][RX];
#pragma unroll
    for (int d = 0; d < NS; d++)
#pragma unroll
        for (int i = 0; i < RX; i++) acc[d][i] = 0.f;

    bar_arrive(BEMPTY0);
    bar_arrive(BEMPTY1);

    int st = 0;
    for (int ch = 0; ch < NCHUNK; ch++) {
        bar_sync(BFULL0 + st);

        const float* s_fa = smem + st * STAGE_FLOATS;
        const float* s_fb = s_fa + FA_FLOATS;

        // register double-buffer across channels
        float4 A0, A1, V0, V1, V2, V3;
        A0 = *(const float4*)(s_fa + faO[0]);
        A1 = *(const float4*)(s_fa + faO[1]);
        V0 = *(const float4*)(s_fb + fbO[0]);
        V1 = *(const float4*)(s_fb + fbO[1]);
        V2 = *(const float4*)(s_fb + fbO[2]);
        V3 = *(const float4*)(s_fb + fbO[3]);

#pragma unroll
        for (int cc = 0; cc < CC; cc++) {
            float4 A0n, A1n, V0n, V1n, V2n, V3n;
            if (cc + 1 < CC) {
                const float* fap = s_fa + (cc + 1) * (TY * Wn);
                const float* fbp = s_fb + (cc + 1) * (FBH * FBW);
                A0n = *(const float4*)(fap + faO[0]);
                A1n = *(const float4*)(fap + faO[1]);
                V0n = *(const float4*)(fbp + fbO[0]);
                V1n = *(const float4*)(fbp + fbO[1]);
                V2n = *(const float4*)(fbp + fbO[2]);
                V3n = *(const float4*)(fbp + fbO[3]);
            }
            float a[RX] = {A0.x, A0.y, A0.z, A0.w, A1.x, A1.y, A1.z, A1.w};
            float v[VW] = {V0.x, V0.y, V0.z, V0.w, V1.x, V1.y, V1.z, V1.w,
                           V2.x, V2.y, V2.z, V2.w, V3.x, V3.y, V3.z, V3.w};
#pragma unroll
            for (int dx = 0; dx < NS; dx++)
#pragma unroll
                for (int i = 0; i < RX; i++)
                    acc[dx][i] = fmaf(a[i], v[dx + i], acc[dx][i]);
            if (cc + 1 < CC) {
                A0 = A0n; A1 = A1n; V0 = V0n; V1 = V1n; V2 = V2n; V3 = V3n;
            }
        }
        bar_arrive(BEMPTY0 + st);
        st ^= 1;
    }

    // wait for producers to publish the norm tiles
    bar_sync(BNORM);

    // ---- epilogue: scale by inverse norms, write 2x float4 per dx ----
    const int y = y0 + yl;
    float ia[RX];
#pragma unroll
    for (int i = 0; i < RX; i++) ia[i] = s_na[yl * Wn + x0 + i];

    float ib[VW];
#pragma unroll
    for (int k = 0; k < VW; k++)
        ib[k] = s_nb[(yl + dy) * FBW + x0 + k];
    // halo/OOB positions: acc is exactly 0 (zfill), so huge ib is harmless

#pragma unroll
    for (int dx = 0; dx < NS; dx++) {
        float o[RX];
#pragma unroll
        for (int i = 0; i < RX; i++)
            o[i] = acc[dx][i] * ia[i] * ib[dx + i];
        const int q = dy * NS + dx;
        float* op = out + ((size_t)(b * Qn + q) * Hn + y) * Wn + x0;
        *(float4*)(op)     = make_float4(o[0], o[1], o[2], o[3]);
        *(float4*)(op + 4) = make_float4(o[4], o[5], o[6], o[7]);
    }
}

// ---------------------------------------------------------------------------
extern "C" void kernel_launch(void* const* d_in, const int* in_sizes, int n_in,
                              void* d_out, int out_size) {
    const float* fa = (const float*)d_in[0];
    const float* fb = (const float*)d_in[1];
    float* out = (float*)d_out;

    cudaFuncSetAttribute(corr_kernel,
                         cudaFuncAttributeMaxDynamicSharedMemorySize,
                         SMEM_BYTES);
    corr_kernel<<<dim3(Hn / TY, Bn), NTHREADS, SMEM_BYTES>>>(fa, fb, out);
}

// round 12
// speedup vs baseline: 1.2844x; 1.2844x over previous
#include <cuda_runtime.h>
#include <cstdint>

// Problem constants
#define Bn 8
#define Cn 256
#define Hn 96
#define Wn 128
#define Dd 4
#define NS 9      // 2*D+1
#define Qn 81     // NS*NS
#define HW (Hn*Wn)

// Tiling: 2 rows per block; RX=8; 288 consumer + 64 producer threads
#define TY 2
#define RX 8
#define XG (Wn/RX)            // 16
#define CONS (TY*XG*NS)       // 288 consumer threads (9 warps)
#define PROD 64               // 2 producer warps
#define NTHREADS (CONS+PROD)  // 352
#define CC 16
#define NCHUNK (Cn/CC)        // 16
#define FBW (Wn + 2*Dd)       // 136
#define FBH (TY + 2*Dd)       // 10
#define VW (RX + 2*Dd)        // 16 window floats per thread

#define FA_FLOATS (CC*TY*Wn)          // 4096
#define FB_FLOATS (CC*FBH*FBW)        // 21760
#define STAGE_FLOATS (FA_FLOATS + FB_FLOATS)   // 25856
#define NORM_FLOATS (TY*Wn)           // 256 (inva tile)
#define SMEM_BYTES ((2*STAGE_FLOATS + NORM_FLOATS)*4)  // 207872

// per-channel loader slots: fa 64, fb 340 -> 404 total
#define FA_SL (TY*(Wn/4))             // 64 (== PROD: one fa slot per producer)
#define FB_SL (FBH*(FBW/4))           // 340
#define TOT_SL (FA_SL+FB_SL)          // 404
#define PSL 7                         // ceil(404/64)

// named barrier ids (0 reserved)
#define BFULL0 1
#define BFULL1 2
#define BEMPTY0 3
#define BEMPTY1 4
#define BNORM 5

// norm_b kernel config
#define NB_THREADS 256
#define NB_SLICES 8
#define NB_CPS (Cn/NB_SLICES)         // 32 channels per slice

// Per-pixel inverse norms for fb (scratch)
__device__ float g_invb[Bn*HW];

// bank-quad swizzle on 16B-unit index within a row
__device__ __host__ __forceinline__ int sw(int u) { return u ^ ((u >> 3) & 1); }

// ---------------------------------------------------------------------------
__device__ __forceinline__ void cp16(uint32_t saddr, const float* g, int nbytes) {
    asm volatile("cp.async.cg.shared.global [%0], [%1], 16, %2;"
                 :: "r"(saddr), "l"(g), "r"(nbytes));
}
__device__ __forceinline__ void bar_sync(int id) {
    asm volatile("bar.sync %0, %1;" :: "r"(id), "n"(NTHREADS) : "memory");
}
__device__ __forceinline__ void bar_arrive(int id) {
    asm volatile("bar.arrive %0, %1;" :: "r"(id), "n"(NTHREADS) : "memory");
}

// ---------------------------------------------------------------------------
// Pass 1: per-pixel inverse L2 norms for fb, channel-split 8-way.
// Block = 32 float2-pixels x 8 channel slices (256 thr); smem reduce.
// ---------------------------------------------------------------------------
__global__ void norm_b_kernel(const float* __restrict__ fb) {
    __shared__ float2 red[NB_THREADS];
    const int b     = blockIdx.y;
    const int lane  = threadIdx.x & 31;      // pixel within block
    const int slice = threadIdx.x >> 5;      // 0..7
    const int p2    = blockIdx.x * 32 + lane;

    const float2* pb = (const float2*)(fb + (size_t)b * Cn * HW) + p2
                     + (size_t)slice * NB_CPS * (HW / 2);
    float s0 = 0.f, s1 = 0.f;
#pragma unroll
    for (int c = 0; c < NB_CPS; c++) {
        float2 v = pb[(size_t)c * (HW / 2)];
        s0 = fmaf(v.x, v.x, s0);
        s1 = fmaf(v.y, v.y, s1);
    }
    red[threadIdx.x] = make_float2(s0, s1);
    __syncthreads();
    if (threadIdx.x < 32) {
        float a0 = 0.f, a1 = 0.f;
#pragma unroll
        for (int s = 0; s < NB_SLICES; s++) {
            float2 v = red[lane + 32 * s];
            a0 += v.x; a1 += v.y;
        }
        float2 o;
        o.x = 1.0f / fmaxf(sqrtf(a0), 1e-12f);
        o.y = 1.0f / fmaxf(sqrtf(a1), 1e-12f);
        ((float2*)g_invb)[b * (HW / 2) + p2] = o;
    }
}

// ---------------------------------------------------------------------------
// Pass 2: warp-specialized correlation, RX=8, swizzled smem. (R10 kernel)
// Producers additionally accumulate fa^2 (their own loaded slots) -> inva
// in smem; consumers read it in the epilogue after a split-phase barrier.
// ---------------------------------------------------------------------------
__global__ void __launch_bounds__(NTHREADS, 1)
corr_kernel(const float* __restrict__ fa,
            const float* __restrict__ fb,
            float* __restrict__ out) {
    extern __shared__ float smem[];

    const int b   = blockIdx.y;
    const int y0  = blockIdx.x * TY;
    const int tid = threadIdx.x;

    const size_t baseA = (size_t)b * Cn * HW;
    const uint32_t smem_u = (uint32_t)__cvta_generic_to_shared(smem);
    float* s_norm = smem + 2 * STAGE_FLOATS;   // inva tile [TY*Wn]

    if (tid >= CONS) {
        // ================= PRODUCER =================
        const int ptid = tid - CONS;   // 0..63
        const float* ld_ptr[PSL];
        int ld_s[PSL], ld_str[PSL], ld_nb[PSL];
#pragma unroll
        for (int k = 0; k < PSL; k++) {
            int slot = ptid + k * PROD;
            ld_ptr[k] = nullptr; ld_s[k] = 0; ld_str[k] = 0; ld_nb[k] = -1;
            if (slot < TOT_SL) {
                if (slot < FA_SL) {
                    int yy = slot / (Wn / 4);
                    int u  = slot % (Wn / 4);
                    ld_nb[k]  = 16;
                    ld_ptr[k] = fa + baseA + (y0 + yy) * Wn + u * 4;
                    ld_s[k]   = yy * Wn + sw(u) * 4;
                    ld_str[k] = TY * Wn;
                } else {
                    int u  = slot - FA_SL;
                    int hr = u / (FBW / 4);
                    int kk = u % (FBW / 4);
                    int yy = y0 - Dd + hr;
                    bool valid = (yy >= 0) && (yy < Hn) && (kk >= 1) && (kk <= Wn / 4);
                    ld_nb[k]  = valid ? 16 : 0;   // zfill halo/OOB
                    int yyc = min(max(yy, 0), Hn - 1);
                    int kc  = min(max(kk, 1), Wn / 4);
                    ld_ptr[k] = fb + baseA + yyc * Wn + kc * 4 - 4;
                    ld_s[k]   = FA_FLOATS + hr * FBW + sw(kk) * 4;
                    ld_str[k] = FBH * FBW;
                }
            }
        }

        // this producer's own fa slot (exactly one: slot == ptid)
        const int fa_yy = ptid / (Wn / 4);
        const int fa_u  = ptid % (Wn / 4);
        const int fa_sofs = fa_yy * Wn + sw(fa_u) * 4;   // smem float offset
        float sq[4] = {0.f, 0.f, 0.f, 0.f};

        int st = 0;
        for (int ch = 0; ch < NCHUNK; ch++) {
            bar_sync(BEMPTY0 + st);
            const int c0 = ch * CC;
            const uint32_t sb = smem_u + (uint32_t)(st * STAGE_FLOATS * 4);
#pragma unroll
            for (int k = 0; k < PSL; k++) {
                if (ld_nb[k] >= 0) {
                    const float* g = ld_ptr[k] + (size_t)c0 * HW;
                    const uint32_t sofs = sb + (uint32_t)(ld_s[k] * 4);
#pragma unroll
                    for (int cc = 0; cc < CC; cc++)
                        cp16(sofs + (uint32_t)(cc * ld_str[k] * 4),
                             g + (size_t)cc * HW, ld_nb[k]);
                }
            }
            asm volatile("cp.async.commit_group;");
            asm volatile("cp.async.wait_group 0;");
            bar_arrive(BFULL0 + st);

            // fa^2 accumulation on this thread's OWN slot (visible after wait)
            const float* sfa = smem + st * STAGE_FLOATS + fa_sofs;
#pragma unroll
            for (int cc = 0; cc < CC; cc++) {
                float4 v = *(const float4*)(sfa + cc * (TY * Wn));
                sq[0] = fmaf(v.x, v.x, sq[0]);
                sq[1] = fmaf(v.y, v.y, sq[1]);
                sq[2] = fmaf(v.z, v.z, sq[2]);
                sq[3] = fmaf(v.w, v.w, sq[3]);
            }
            st ^= 1;
        }

        // publish inva for this thread's 4 pixels
        float4 iv;
        iv.x = 1.0f / fmaxf(sqrtf(sq[0]), 1e-12f);
        iv.y = 1.0f / fmaxf(sqrtf(sq[1]), 1e-12f);
        iv.z = 1.0f / fmaxf(sqrtf(sq[2]), 1e-12f);
        iv.w = 1.0f / fmaxf(sqrtf(sq[3]), 1e-12f);
        *(float4*)(s_norm + fa_yy * Wn + fa_u * 4) = iv;
        bar_arrive(BNORM);
        return;
    }

    // ================= CONSUMER =================
    const int dy = tid / 32;                 // 0..8 (one dy per warp)
    const int r  = tid % 32;
    const int yl = r / XG;                   // 0..1
    const int xg = r % XG;                   // 0..15
    const int x0 = xg * RX;

    // swizzled, channel-invariant float offsets
    int faO[2], fbO[4];
#pragma unroll
    for (int j = 0; j < 2; j++)
        faO[j] = yl * Wn + sw(2 * xg + j) * 4;
#pragma unroll
    for (int j = 0; j < 4; j++)
        fbO[j] = (yl + dy) * FBW + sw(2 * xg + j) * 4;

    float acc[NS][RX];
#pragma unroll
    for (int d = 0; d < NS; d++)
#pragma unroll
        for (int i = 0; i < RX; i++) acc[d][i] = 0.f;

    bar_arrive(BEMPTY0);
    bar_arrive(BEMPTY1);

    int st = 0;
    for (int ch = 0; ch < NCHUNK; ch++) {
        bar_sync(BFULL0 + st);

        const float* s_fa = smem + st * STAGE_FLOATS;
        const float* s_fb = s_fa + FA_FLOATS;

        // register double-buffer across channels
        float4 A0, A1, V0, V1, V2, V3;
        A0 = *(const float4*)(s_fa + faO[0]);
        A1 = *(const float4*)(s_fa + faO[1]);
        V0 = *(const float4*)(s_fb + fbO[0]);
        V1 = *(const float4*)(s_fb + fbO[1]);
        V2 = *(const float4*)(s_fb + fbO[2]);
        V3 = *(const float4*)(s_fb + fbO[3]);

#pragma unroll
        for (int cc = 0; cc < CC; cc++) {
            float4 A0n, A1n, V0n, V1n, V2n, V3n;
            if (cc + 1 < CC) {
                const float* fap = s_fa + (cc + 1) * (TY * Wn);
                const float* fbp = s_fb + (cc + 1) * (FBH * FBW);
                A0n = *(const float4*)(fap + faO[0]);
                A1n = *(const float4*)(fap + faO[1]);
                V0n = *(const float4*)(fbp + fbO[0]);
                V1n = *(const float4*)(fbp + fbO[1]);
                V2n = *(const float4*)(fbp + fbO[2]);
                V3n = *(const float4*)(fbp + fbO[3]);
            }
            float a[RX] = {A0.x, A0.y, A0.z, A0.w, A1.x, A1.y, A1.z, A1.w};
            float v[VW] = {V0.x, V0.y, V0.z, V0.w, V1.x, V1.y, V1.z, V1.w,
                           V2.x, V2.y, V2.z, V2.w, V3.x, V3.y, V3.z, V3.w};
#pragma unroll
            for (int dx = 0; dx < NS; dx++)
#pragma unroll
                for (int i = 0; i < RX; i++)
                    acc[dx][i] = fmaf(a[i], v[dx + i], acc[dx][i]);
            if (cc + 1 < CC) {
                A0 = A0n; A1 = A1n; V0 = V0n; V1 = V1n; V2 = V2n; V3 = V3n;
            }
        }
        bar_arrive(BEMPTY0 + st);
        st ^= 1;
    }

    // wait for producers to publish inva
    bar_sync(BNORM);

    // ---- epilogue: scale by inverse norms, write 2x float4 per dx ----
    const int y = y0 + yl;
    float ia[RX];
#pragma unroll
    for (int i = 0; i < RX; i++) ia[i] = s_norm[yl * Wn + x0 + i];

    const int sy = y + dy - Dd;
    const bool rowok = (unsigned)sy < (unsigned)Hn;
    float ib[VW];
#pragma unroll
    for (int k = 0; k < VW; k++) {
        int sx = x0 + k - Dd;
        ib[k] = (rowok && (unsigned)sx < (unsigned)Wn)
                    ? g_invb[b * HW + sy * Wn + sx] : 0.f;
        // raw acc is exactly 0 for OOB (zfill halo), so ib=0 is safe
    }

#pragma unroll
    for (int dx = 0; dx < NS; dx++) {
        float o[RX];
#pragma unroll
        for (int i = 0; i < RX; i++)
            o[i] = acc[dx][i] * ia[i] * ib[dx + i];
        const int q = dy * NS + dx;
        float* op = out + ((size_t)(b * Qn + q) * Hn + y) * Wn + x0;
        *(float4*)(op)     = make_float4(o[0], o[1], o[2], o[3]);
        *(float4*)(op + 4) = make_float4(o[4], o[5], o[6], o[7]);
    }
}

// ---------------------------------------------------------------------------
extern "C" void kernel_launch(void* const* d_in, const int* in_sizes, int n_in,
                              void* d_out, int out_size) {
    const float* fa = (const float*)d_in[0];
    const float* fb = (const float*)d_in[1];
    float* out = (float*)d_out;

    norm_b_kernel<<<dim3(HW / 2 / 32, Bn), NB_THREADS>>>(fb);

    cudaFuncSetAttribute(corr_kernel,
                         cudaFuncAttributeMaxDynamicSharedMemorySize,
                         SMEM_BYTES);
    corr_kernel<<<dim3(Hn / TY, Bn), NTHREADS, SMEM_BYTES>>>(fa, fb, out);
}